// round 15
// baseline (speedup 1.0000x reference)
#include <cuda_runtime.h>
#include <cstdint>
#include <cstddef>

#define N_NODES 4096
#define IN_FEAT 256
#define N_HEADS 8
#define N_HIDDEN 32
#define OUT_FEAT 256   // N_HEADS * N_HIDDEN
#define JSPLIT 7
#define LOG2E 1.4426950408889634f

// Scratch (static __device__ globals: allocation-free per harness rules)
__device__ float d_si[N_NODES * N_HEADS];            // s_i[n][h] * log2(e)
__device__ float d_sj[N_NODES * N_HEADS];            // s_j[n][h] * log2(e)
__device__ unsigned d_gfrag[N_HEADS * 512 * 32 * 8]; // 4 MB: tf32 B-fragments
__device__ float d_part[JSPLIT][N_NODES * OUT_FEAT]; // 28 MB partial outputs
__device__ float d_rs[JSPLIT][N_NODES * N_HEADS];    // partial row sums

__device__ __forceinline__ unsigned cvt_tf32(float x) {
    unsigned r;
    asm("cvt.rna.tf32.f32 %0, %1;" : "=r"(r) : "f"(x));
    return r;
}
__device__ __forceinline__ float ex2(float x) {
    float r;
    asm("ex2.approx.f32 %0, %1;" : "=f"(r) : "f"(x));
    return r;
}
__device__ __forceinline__ void mma_tf32(float* c, unsigned a0, unsigned a1,
                                         unsigned a2, unsigned a3,
                                         unsigned b0, unsigned b1) {
    asm volatile(
        "mma.sync.aligned.m16n8k8.row.col.f32.tf32.tf32.f32 "
        "{%0,%1,%2,%3}, {%4,%5,%6,%7}, {%8,%9}, {%0,%1,%2,%3};"
        : "+f"(c[0]), "+f"(c[1]), "+f"(c[2]), "+f"(c[3])
        : "r"(a0), "r"(a1), "r"(a2), "r"(a3), "r"(b0), "r"(b1));
}

// ---------------------------------------------------------------------------
// Kernel 1 (fused, tensor-core, NOW DOUBLE-BUFFERED): g = h @ W^T for one
// (64-row, 2-head) tile via tf32 mma.m16n8k8. LDG of tile k+1 issues before
// the MMAs of tile k (register-held), STS into the alternate smem stage, one
// __syncthreads per iteration. Fused epilogues unchanged:
//   A) s_i/s_j from fp32 C-fragments + tig-shfl reduce
//   B) tf32 B-fragment pack for both heads straight to d_gfrag
// grid (64, 4) = 256 CTAs, 256 threads = 8 warps.
// ---------------------------------------------------------------------------
__global__ __launch_bounds__(256) void gemm_fused_kernel(const float* __restrict__ h,
                                                         const float* __restrict__ W,
                                                         const float* __restrict__ a) {
    __shared__ __align__(16) float buf[9216];    // 2 stages x (As 2304 + Bs 2304)

    const int n0 = blockIdx.x * 64;
    const int by = blockIdx.y;               // head pair: heads 2by, 2by+1
    const int o0 = by * 64;
    const int t  = threadIdx.x;
    const int w  = t >> 5;
    const int lane = t & 31;
    const int wr = w >> 1;       // 16-row block 0..3
    const int wc = w & 1;        // 32-col block (head within pair)
    const int gid = lane >> 2, tig = lane & 3;
    const int c4s = t & 7;       // staging float4-column

    float4 rA[2], rB[2];
    // load k-tile 0 into registers
#pragma unroll
    for (int rep = 0; rep < 2; rep++) {
        int r = (t >> 3) + rep * 32;
        rA[rep] = *(const float4*)(h + (size_t)(n0 + r) * IN_FEAT + c4s * 4);
        rB[rep] = *(const float4*)(W + (size_t)(o0 + r) * IN_FEAT + c4s * 4);
    }
    // store stage 0 (tf32-converted)
#pragma unroll
    for (int rep = 0; rep < 2; rep++) {
        int r = (t >> 3) + rep * 32;
        uint4 ua; ua.x = cvt_tf32(rA[rep].x); ua.y = cvt_tf32(rA[rep].y);
        ua.z = cvt_tf32(rA[rep].z); ua.w = cvt_tf32(rA[rep].w);
        *(uint4*)(buf + r * 36 + c4s * 4) = ua;
        uint4 ub; ub.x = cvt_tf32(rB[rep].x); ub.y = cvt_tf32(rB[rep].y);
        ub.z = cvt_tf32(rB[rep].z); ub.w = cvt_tf32(rB[rep].w);
        *(uint4*)(buf + 2304 + r * 36 + c4s * 4) = ub;
    }
    __syncthreads();

    float acc[4][4] = {};        // [nt][c0..c3]

#pragma unroll
    for (int ki = 0; ki < 8; ki++) {
        const int cur = ki & 1;
        if (ki < 7) {            // prefetch tile ki+1 into registers
            const int k0 = (ki + 1) * 32;
#pragma unroll
            for (int rep = 0; rep < 2; rep++) {
                int r = (t >> 3) + rep * 32;
                rA[rep] = *(const float4*)(h + (size_t)(n0 + r) * IN_FEAT + k0 + c4s * 4);
                rB[rep] = *(const float4*)(W + (size_t)(o0 + r) * IN_FEAT + k0 + c4s * 4);
            }
        }
        // MMAs from stage cur
        const unsigned* Au = (const unsigned*)(buf + cur * 4608);
        const unsigned* Bu = Au + 2304;
        const int arow0 = (wr * 16 + gid) * 36;
        const int arow1 = arow0 + 8 * 36;
        const int brow  = (wc * 32 + gid) * 36;
#pragma unroll
        for (int ks = 0; ks < 4; ks++) {
            const int kk = ks * 8 + tig;
            unsigned a0 = Au[arow0 + kk];
            unsigned a1 = Au[arow1 + kk];
            unsigned a2 = Au[arow0 + kk + 4];
            unsigned a3 = Au[arow1 + kk + 4];
#pragma unroll
            for (int nt = 0; nt < 4; nt++) {
                unsigned b0 = Bu[brow + nt * 8 * 36 + kk];
                unsigned b1 = Bu[brow + nt * 8 * 36 + kk + 4];
                mma_tf32(acc[nt], a0, a1, a2, a3, b0, b1);
            }
        }
        if (ki < 7) {            // store prefetched tile into the other stage
            float* dstA = buf + (cur ^ 1) * 4608;
            float* dstB = dstA + 2304;
#pragma unroll
            for (int rep = 0; rep < 2; rep++) {
                int r = (t >> 3) + rep * 32;
                uint4 ua; ua.x = cvt_tf32(rA[rep].x); ua.y = cvt_tf32(rA[rep].y);
                ua.z = cvt_tf32(rA[rep].z); ua.w = cvt_tf32(rA[rep].w);
                *(uint4*)(dstA + r * 36 + c4s * 4) = ua;
                uint4 ub; ub.x = cvt_tf32(rB[rep].x); ub.y = cvt_tf32(rB[rep].y);
                ub.z = cvt_tf32(rB[rep].z); ub.w = cvt_tf32(rB[rep].w);
                *(uint4*)(dstB + r * 36 + c4s * 4) = ub;
            }
            __syncthreads();
        }
    }

    // --- epilogue A: s_i/s_j from C fragments (warp covers one head) ---
    {
        float ps[4] = {0.f, 0.f, 0.f, 0.f};   // si_r0, sj_r0, si_r1, sj_r1
#pragma unroll
        for (int nt = 0; nt < 4; nt++) {
            int c0 = nt * 8 + 2 * tig;
            float al0 = __ldg(a + c0),      al1 = __ldg(a + c0 + 1);
            float ar0 = __ldg(a + 32 + c0), ar1 = __ldg(a + 32 + c0 + 1);
            ps[0] += acc[nt][0] * al0 + acc[nt][1] * al1;
            ps[1] += acc[nt][0] * ar0 + acc[nt][1] * ar1;
            ps[2] += acc[nt][2] * al0 + acc[nt][3] * al1;
            ps[3] += acc[nt][2] * ar0 + acc[nt][3] * ar1;
        }
#pragma unroll
        for (int off = 1; off < 4; off <<= 1)
#pragma unroll
            for (int q = 0; q < 4; q++)
                ps[q] += __shfl_xor_sync(0xffffffffu, ps[q], off);
        if (tig == 0) {
            int head = 2 * by + wc;
            int r0 = n0 + wr * 16 + gid;
            d_si[(size_t)r0 * N_HEADS + head]       = ps[0] * LOG2E;
            d_sj[(size_t)r0 * N_HEADS + head]       = ps[1] * LOG2E;
            d_si[(size_t)(r0 + 8) * N_HEADS + head] = ps[2] * LOG2E;
            d_sj[(size_t)(r0 + 8) * N_HEADS + head] = ps[3] * LOG2E;
        }
    }

    // --- epilogue B: re-stage g to smem (stride 72), pack tf32 fragments ---
    // stage0 (buf[0..4608)) was last read at ki==6, all warps past that sync;
    // ki==7 MMAs read stage1 only -> writing gS over stage0 is race-free.
    float* gS = buf;                 // [64][72] = 4608 floats
#pragma unroll
    for (int nt = 0; nt < 4; nt++) {
        int col = wc * 32 + nt * 8 + 2 * tig;
        int r0  = wr * 16 + gid;
        *(float2*)(gS + r0 * 72 + col)       = make_float2(acc[nt][0], acc[nt][1]);
        *(float2*)(gS + (r0 + 8) * 72 + col) = make_float2(acc[nt][2], acc[nt][3]);
    }
    __syncthreads();

#pragma unroll
    for (int rep = 0; rep < 2; rep++) {
        int grp = (t >> 5) + rep * 8;    // 0..15: hd = grp>>3, ktg = grp&7
        int hd  = grp >> 3;
        int ktg = grp & 7;
        unsigned v[8];
#pragma unroll
        for (int nt = 0; nt < 4; nt++)
#pragma unroll
            for (int half = 0; half < 2; half++)
                v[nt * 2 + half] = cvt_tf32(
                    gS[(ktg * 8 + half * 4 + tig) * 72 + hd * 32 + nt * 8 + gid]);
        size_t gt = ((size_t)(2 * by + hd) * 512 + (n0 >> 3) + ktg) * 32 + lane;
        uint4* dst = (uint4*)d_gfrag + gt * 2;
        dst[0] = make_uint4(v[0], v[1], v[2], v[3]);
        dst[1] = make_uint4(v[4], v[5], v[6], v[7]);
    }
}

// ---------------------------------------------------------------------------
// Kernel 2: attention. Grid (128, JSPLIT) = 896 CTAs, 256 threads = 8 warps
// (warp = head), launch_bounds(256,3).
// exp(lrelu(si+sj)) == max(Ei*Ej, Fi*Fj) -> no MUFU in hot loop.
// NEW: (a) q-fragment LDG prefetched one kt ahead (cross-jt wrap, clamped);
//      (b) mask path = arithmetic sign-mask + single LOP3:
//          m = (int)(mrow << (31-sh)) >> 31;  a = w & m & 0xFFFFE000
//        bit-identical to the old ISETP/SEL path, 1 fewer alu op and no
//        predicate latency. rs FADDs see exactly the MMA operand bits.
// ---------------------------------------------------------------------------
__global__ __launch_bounds__(256, 3) void attn_kernel(const int* __restrict__ adj) {
    __shared__ float2 efS[N_HEADS * 64];   // (Ej, Fj) per [h][j_local]
    __shared__ unsigned adjLo[32];         // bits j0..j0+31 for 32 i-rows
    __shared__ unsigned adjHi[32];         // bits j0+32..j0+63

    const int i0   = blockIdx.x * 32;
    const int js   = blockIdx.y;           // 0..JSPLIT-1
    const int tid  = threadIdx.x;
    const int w    = tid >> 5;             // warp = head
    const int h    = w;
    const int lane = tid & 31;
    const int gid  = lane >> 2;
    const int tig  = lane & 3;

    float Ei[4], Fi[4];
#pragma unroll
    for (int m = 0; m < 4; m++) {
        float s = d_si[(size_t)(i0 + m * 8 + gid) * N_HEADS + h];
        Ei[m] = ex2(s);
        Fi[m] = ex2(0.2f * s);
    }

    float acc[2][4][4] = {};
    float rs[4] = {0.f, 0.f, 0.f, 0.f};

    const uint4* fragbase = (const uint4*)d_gfrag + (size_t)h * 512 * 32 * 2;

    // prefetch first fragment (jt=js, kt=0)
    uint4 q0, q1;
    {
        const uint4* fb = fragbase + ((size_t)(js * 8) * 32 + lane) * 2;
        q0 = __ldg(fb); q1 = __ldg(fb + 1);
    }

    for (int jt = js; jt < 64; jt += JSPLIT) {
        const int j0 = jt * 64;
        __syncthreads();
#pragma unroll
        for (int rep = 0; rep < 2; rep++) {
            int idx = tid + rep * 256;
            int jl = idx >> 3, hh = idx & 7;
            float sj = d_sj[(size_t)(j0 + jl) * N_HEADS + hh];
            efS[hh * 64 + jl] = make_float2(ex2(sj), ex2(0.2f * sj));
        }
#pragma unroll
        for (int rr = 0; rr < 4; rr++) {
            int r = w * 4 + rr;
            const int* arow = adj + (size_t)(i0 + r) * N_NODES + j0;
            unsigned b0 = __ballot_sync(0xffffffffu, arow[lane] != 0);
            unsigned b1 = __ballot_sync(0xffffffffu, arow[32 + lane] != 0);
            if (lane == 0) { adjLo[r] = b0; adjHi[r] = b1; }
        }
        __syncthreads();

        unsigned mrow[4];
#pragma unroll
        for (int kt = 0; kt < 8; kt++) {
            if (kt == 0) {
                mrow[0] = adjLo[gid];      mrow[1] = adjLo[8 + gid];
                mrow[2] = adjLo[16 + gid]; mrow[3] = adjLo[24 + gid];
            }
            if (kt == 4) {
                mrow[0] = adjHi[gid];      mrow[1] = adjHi[8 + gid];
                mrow[2] = adjHi[16 + gid]; mrow[3] = adjHi[24 + gid];
            }
            // prefetch next fragment: next kt, or next jt's kt0 (clamped)
            int nidx;
            if (kt < 7) {
                nidx = jt * 8 + kt + 1;
            } else {
                int jn = jt + JSPLIT;
                nidx = (jn < 64) ? jn * 8 : jt * 8;
            }
            const uint4* fn = fragbase + ((size_t)nidx * 32 + lane) * 2;
            uint4 p0 = __ldg(fn), p1 = __ldg(fn + 1);

            float2 ef0 = efS[h * 64 + kt * 8 + tig];
            float2 ef1 = efS[h * 64 + kt * 8 + tig + 4];
            const int shA = 31 - (kt & 3) * 8 - tig;   // col tig bit -> bit 31
            const int shB = shA - 4;                   // col tig+4 bit -> bit 31

#pragma unroll
            for (int mt = 0; mt < 2; mt++) {
                unsigned m00 = (unsigned)((int)(mrow[2 * mt]     << shA) >> 31);
                unsigned m01 = (unsigned)((int)(mrow[2 * mt]     << shB) >> 31);
                unsigned m10 = (unsigned)((int)(mrow[2 * mt + 1] << shA) >> 31);
                unsigned m11 = (unsigned)((int)(mrow[2 * mt + 1] << shB) >> 31);

                float w00 = fmaxf(Ei[2 * mt]     * ef0.x, Fi[2 * mt]     * ef0.y);
                float w01 = fmaxf(Ei[2 * mt]     * ef1.x, Fi[2 * mt]     * ef1.y);
                float w10 = fmaxf(Ei[2 * mt + 1] * ef0.x, Fi[2 * mt + 1] * ef0.y);
                float w11 = fmaxf(Ei[2 * mt + 1] * ef1.x, Fi[2 * mt + 1] * ef1.y);

                unsigned a0 = __float_as_uint(w00) & m00 & 0xFFFFE000u;  // one LOP3
                unsigned a2 = __float_as_uint(w01) & m01 & 0xFFFFE000u;
                unsigned a1 = __float_as_uint(w10) & m10 & 0xFFFFE000u;
                unsigned a3 = __float_as_uint(w11) & m11 & 0xFFFFE000u;

                rs[2 * mt]     += __uint_as_float(a0) + __uint_as_float(a2);
                rs[2 * mt + 1] += __uint_as_float(a1) + __uint_as_float(a3);

                mma_tf32(acc[mt][0], a0, a1, a2, a3, q0.x, q0.y);
                mma_tf32(acc[mt][1], a0, a1, a2, a3, q0.z, q0.w);
                mma_tf32(acc[mt][2], a0, a1, a2, a3, q1.x, q1.y);
                mma_tf32(acc[mt][3], a0, a1, a2, a3, q1.z, q1.w);
            }
            q0 = p0; q1 = p1;
        }
    }

#pragma unroll
    for (int m = 0; m < 4; m++) {
        rs[m] += __shfl_xor_sync(0xffffffffu, rs[m], 1);
        rs[m] += __shfl_xor_sync(0xffffffffu, rs[m], 2);
    }
    if (tig == 0) {
#pragma unroll
        for (int m = 0; m < 4; m++)
            d_rs[js][(size_t)(i0 + m * 8 + gid) * N_HEADS + h] = rs[m];
    }
#pragma unroll
    for (int mt = 0; mt < 2; mt++) {
        int r0 = i0 + mt * 16 + gid;
        int r1 = r0 + 8;
#pragma unroll
        for (int nt = 0; nt < 4; nt++) {
            int c = h * N_HIDDEN + nt * 8 + tig * 2;
            *(float2*)(&d_part[js][(size_t)r0 * OUT_FEAT + c]) =
                make_float2(acc[mt][nt][0], acc[mt][nt][1]);
            *(float2*)(&d_part[js][(size_t)r1 * OUT_FEAT + c]) =
                make_float2(acc[mt][nt][2], acc[mt][nt][3]);
        }
    }
}

// ---------------------------------------------------------------------------
// Kernel 3: reduce partials and normalize (unchanged).
// ---------------------------------------------------------------------------
__global__ __launch_bounds__(256) void reduce_kernel(float* __restrict__ out) {
    int t  = blockIdx.x * 256 + threadIdx.x;   // 0..262143
    int i  = t >> 6;
    int c4 = t & 63;
    int hh = c4 >> 3;

    float4 num = make_float4(0.f, 0.f, 0.f, 0.f);
    float den = 0.f;
#pragma unroll
    for (int s = 0; s < JSPLIT; s++) {
        float4 p = *(const float4*)(&d_part[s][(size_t)i * OUT_FEAT + c4 * 4]);
        num.x += p.x; num.y += p.y; num.z += p.z; num.w += p.w;
        den += d_rs[s][(size_t)i * N_HEADS + hh];
    }
    float inv = 1.0f / den;
    *(float4*)(out + (size_t)i * OUT_FEAT + c4 * 4) =
        make_float4(num.x * inv, num.y * inv, num.z * inv, num.w * inv);
}

// ---------------------------------------------------------------------------
// Launch
// ---------------------------------------------------------------------------
extern "C" void kernel_launch(void* const* d_in, const int* in_sizes, int n_in,
                              void* d_out, int out_size) {
    const float* h   = (const float*)d_in[0];   // [4096, 256]
    const float* W   = (const float*)d_in[1];   // [256, 256]
    const float* a   = (const float*)d_in[2];   // [64]
    const int*   adj = (const int*)d_in[3];     // [4096, 4096, 1]
    float* out = (float*)d_out;                 // [4096, 256]

    (void)in_sizes; (void)n_in; (void)out_size;

    dim3 g1(N_NODES / 64, N_HEADS / 2);
    gemm_fused_kernel<<<g1, 256>>>(h, W, a);

    attn_kernel<<<dim3(N_NODES / 32, JSPLIT), 256>>>(adj);

    reduce_kernel<<<(N_NODES * OUT_FEAT / 4) / 256, 256>>>(out);
}

// round 16
// speedup vs baseline: 1.8328x; 1.8328x over previous
#include <cuda_runtime.h>
#include <cstdint>
#include <cstddef>

#define N_NODES 4096
#define IN_FEAT 256
#define N_HEADS 8
#define N_HIDDEN 32
#define OUT_FEAT 256   // N_HEADS * N_HIDDEN
#define JSPLIT 7
#define LOG2E 1.4426950408889634f

// Scratch (static __device__ globals: allocation-free per harness rules)
__device__ float d_si[N_NODES * N_HEADS];            // s_i[n][h] * log2(e)
__device__ float d_sj[N_NODES * N_HEADS];            // s_j[n][h] * log2(e)
__device__ unsigned d_gfrag[N_HEADS * 512 * 32 * 8]; // 4 MB: tf32 B-fragments
__device__ float d_part[JSPLIT][N_NODES * OUT_FEAT]; // 28 MB partial outputs
__device__ float d_rs[JSPLIT][N_NODES * N_HEADS];    // partial row sums

__device__ __forceinline__ unsigned cvt_tf32(float x) {
    unsigned r;
    asm("cvt.rna.tf32.f32 %0, %1;" : "=r"(r) : "f"(x));
    return r;
}
__device__ __forceinline__ float ex2(float x) {
    float r;
    asm("ex2.approx.f32 %0, %1;" : "=f"(r) : "f"(x));
    return r;
}
__device__ __forceinline__ void mma_tf32(float* c, unsigned a0, unsigned a1,
                                         unsigned a2, unsigned a3,
                                         unsigned b0, unsigned b1) {
    asm volatile(
        "mma.sync.aligned.m16n8k8.row.col.f32.tf32.tf32.f32 "
        "{%0,%1,%2,%3}, {%4,%5,%6,%7}, {%8,%9}, {%0,%1,%2,%3};"
        : "+f"(c[0]), "+f"(c[1]), "+f"(c[2]), "+f"(c[3])
        : "r"(a0), "r"(a1), "r"(a2), "r"(a3), "r"(b0), "r"(b1));
}

// ---------------------------------------------------------------------------
// Kernel 1 (fused, tensor-core, 512 THREADS): g = h @ W^T for one
// (64-row, 2-head) tile via tf32 mma.m16n8k8. Single-buffered (R14 proven
// structure) but 16 warps with M16xN16 warp tiles -> ~27 warps/SM to hide
// the LDG->STS->sync->MMA latency chain that capped R14 at issue 19.7%.
// Epilogues via the gS smem stage:
//   A) s_i/s_j: 8-col/thread dot + 4-lane shfl reduce
//   B) tf32 B-fragment pack: 16 warps = 16 (hd,ktg) groups
// grid (64, 4) = 256 CTAs. g accumulation bit-identical to R14.
// ---------------------------------------------------------------------------
__global__ __launch_bounds__(512) void gemm_fused_kernel(const float* __restrict__ h,
                                                         const float* __restrict__ W,
                                                         const float* __restrict__ a) {
    __shared__ __align__(16) float buf[4608];    // As(64*36) + Bs(64*36); reused as gS(64*72)
    float* As = buf;            // [64][36] tf32 bits of h tile rows
    float* Bs = buf + 2304;     // [64][36] tf32 bits of W tile rows

    const int n0 = blockIdx.x * 64;
    const int by = blockIdx.y;               // head pair: heads 2by, 2by+1
    const int o0 = by * 64;
    const int t  = threadIdx.x;
    const int w  = t >> 5;       // 16 warps
    const int lane = t & 31;
    const int wr = w >> 2;       // 16-row block 0..3
    const int wc = w & 3;        // 16-col block 0..3
    const int gid = lane >> 2, tig = lane & 3;
    const int rstg = t >> 3;     // staging row 0..63
    const int c4s  = t & 7;      // staging float4-column

    float acc[2][4] = {};        // [nt][c0..c3]

    for (int ki = 0; ki < 8; ki++) {
        const int k0 = ki * 32;
        // one float4 of A and B per thread covers the whole 64x32 tiles
        float4 av = *(const float4*)(h + (size_t)(n0 + rstg) * IN_FEAT + k0 + c4s * 4);
        float4 bv = *(const float4*)(W + (size_t)(o0 + rstg) * IN_FEAT + k0 + c4s * 4);
        __syncthreads();         // prior MMAs done before overwrite
        uint4 ua;
        ua.x = cvt_tf32(av.x); ua.y = cvt_tf32(av.y);
        ua.z = cvt_tf32(av.z); ua.w = cvt_tf32(av.w);
        *(uint4*)(As + rstg * 36 + c4s * 4) = ua;
        uint4 ub;
        ub.x = cvt_tf32(bv.x); ub.y = cvt_tf32(bv.y);
        ub.z = cvt_tf32(bv.z); ub.w = cvt_tf32(bv.w);
        *(uint4*)(Bs + rstg * 36 + c4s * 4) = ub;
        __syncthreads();

        const unsigned* Au = (const unsigned*)As;
        const unsigned* Bu = (const unsigned*)Bs;
        const int arow0 = (wr * 16 + gid) * 36;
        const int arow1 = arow0 + 8 * 36;
        const int brow  = (wc * 16 + gid) * 36;
#pragma unroll
        for (int ks = 0; ks < 4; ks++) {
            const int kk = ks * 8 + tig;
            unsigned a0 = Au[arow0 + kk];
            unsigned a1 = Au[arow1 + kk];
            unsigned a2 = Au[arow0 + kk + 4];
            unsigned a3 = Au[arow1 + kk + 4];
            mma_tf32(acc[0], a0, a1, a2, a3, Bu[brow + kk], Bu[brow + kk + 4]);
            mma_tf32(acc[1], a0, a1, a2, a3,
                     Bu[brow + 8 * 36 + kk], Bu[brow + 8 * 36 + kk + 4]);
        }
    }
    __syncthreads();             // all MMAs done before gS overwrites As/Bs

    // --- stage C to gS [64][72] ---
    float* gS = buf;
#pragma unroll
    for (int nt = 0; nt < 2; nt++) {
        int col = wc * 16 + nt * 8 + 2 * tig;
        int r0  = wr * 16 + gid;
        *(float2*)(gS + r0 * 72 + col)       = make_float2(acc[nt][0], acc[nt][1]);
        *(float2*)(gS + (r0 + 8) * 72 + col) = make_float2(acc[nt][2], acc[nt][3]);
    }
    __syncthreads();

    // --- epilogue A: s_i/s_j from gS ---
    // thread t: row r = t>>3, sub = t&7 -> head hd = sub>>2, quarter q = sub&3
    {
        int r   = t >> 3;
        int sub = t & 7;
        int hd  = sub >> 2;
        int q   = sub & 3;
        const float* grow = gS + r * 72 + hd * 32 + q * 8;
        float si = 0.f, sj = 0.f;
#pragma unroll
        for (int j = 0; j < 8; j++) {
            float gv = grow[j];
            si = fmaf(gv, __ldg(a + q * 8 + j), si);
            sj = fmaf(gv, __ldg(a + 32 + q * 8 + j), sj);
        }
        // reduce over q (lane bits 0-1; stays within same (r, hd) group)
        si += __shfl_xor_sync(0xffffffffu, si, 1);
        si += __shfl_xor_sync(0xffffffffu, si, 2);
        sj += __shfl_xor_sync(0xffffffffu, sj, 1);
        sj += __shfl_xor_sync(0xffffffffu, sj, 2);
        if (q == 0) {
            int head = 2 * by + hd;
            d_si[(size_t)(n0 + r) * N_HEADS + head] = si * LOG2E;
            d_sj[(size_t)(n0 + r) * N_HEADS + head] = sj * LOG2E;
        }
    }

    // --- epilogue B: pack tf32 fragments (16 warps = 16 (hd,ktg) groups) ---
    {
        int hd  = w >> 3;
        int ktg = w & 7;
        unsigned v[8];
#pragma unroll
        for (int nt = 0; nt < 4; nt++)
#pragma unroll
            for (int half = 0; half < 2; half++)
                v[nt * 2 + half] = cvt_tf32(
                    gS[(ktg * 8 + half * 4 + tig) * 72 + hd * 32 + nt * 8 + gid]);
        size_t gt = ((size_t)(2 * by + hd) * 512 + (n0 >> 3) + ktg) * 32 + lane;
        uint4* dst = (uint4*)d_gfrag + gt * 2;
        dst[0] = make_uint4(v[0], v[1], v[2], v[3]);
        dst[1] = make_uint4(v[4], v[5], v[6], v[7]);
    }
}

// ---------------------------------------------------------------------------
// Kernel 2: attention — EXACT R13/R14 version (114.8us config). Grid
// (128, JSPLIT) = 896 CTAs, 256 threads = 8 warps (warp = head),
// launch_bounds(256,3). exp(lrelu(si+sj)) == max(Ei*Ej, Fi*Fj) -> no MUFU.
// Row sums via FADD of masked, explicitly tf32-truncated weights.
// ---------------------------------------------------------------------------
__global__ __launch_bounds__(256, 3) void attn_kernel(const int* __restrict__ adj) {
    __shared__ float2 efS[N_HEADS * 64];   // (Ej, Fj) per [h][j_local]
    __shared__ unsigned adjLo[32];         // bits j0..j0+31 for 32 i-rows
    __shared__ unsigned adjHi[32];         // bits j0+32..j0+63

    const int i0   = blockIdx.x * 32;
    const int js   = blockIdx.y;           // 0..JSPLIT-1
    const int tid  = threadIdx.x;
    const int w    = tid >> 5;             // warp = head
    const int h    = w;
    const int lane = tid & 31;
    const int gid  = lane >> 2;
    const int tig  = lane & 3;

    float Ei[4], Fi[4];
#pragma unroll
    for (int m = 0; m < 4; m++) {
        float s = d_si[(size_t)(i0 + m * 8 + gid) * N_HEADS + h];
        Ei[m] = ex2(s);
        Fi[m] = ex2(0.2f * s);
    }

    float acc[2][4][4] = {};
    float rs[4] = {0.f, 0.f, 0.f, 0.f};

    const uint4* fragbase = (const uint4*)d_gfrag + (size_t)h * 512 * 32 * 2;

    for (int jt = js; jt < 64; jt += JSPLIT) {
        const int j0 = jt * 64;
        __syncthreads();
#pragma unroll
        for (int rep = 0; rep < 2; rep++) {
            int idx = tid + rep * 256;
            int jl = idx >> 3, hh = idx & 7;
            float sj = d_sj[(size_t)(j0 + jl) * N_HEADS + hh];
            efS[hh * 64 + jl] = make_float2(ex2(sj), ex2(0.2f * sj));
        }
#pragma unroll
        for (int rr = 0; rr < 4; rr++) {
            int r = w * 4 + rr;
            const int* arow = adj + (size_t)(i0 + r) * N_NODES + j0;
            unsigned b0 = __ballot_sync(0xffffffffu, arow[lane] != 0);
            unsigned b1 = __ballot_sync(0xffffffffu, arow[32 + lane] != 0);
            if (lane == 0) { adjLo[r] = b0; adjHi[r] = b1; }
        }
        __syncthreads();

        unsigned mrow[4];
#pragma unroll
        for (int kt = 0; kt < 8; kt++) {
            if (kt == 0) {
                mrow[0] = adjLo[gid];      mrow[1] = adjLo[8 + gid];
                mrow[2] = adjLo[16 + gid]; mrow[3] = adjLo[24 + gid];
            }
            if (kt == 4) {
                mrow[0] = adjHi[gid];      mrow[1] = adjHi[8 + gid];
                mrow[2] = adjHi[16 + gid]; mrow[3] = adjHi[24 + gid];
            }
            const uint4* fb = fragbase + ((size_t)(jt * 8 + kt) * 32 + lane) * 2;
            uint4 q0 = __ldg(fb);
            uint4 q1 = __ldg(fb + 1);
            float2 ef0 = efS[h * 64 + kt * 8 + tig];
            float2 ef1 = efS[h * 64 + kt * 8 + tig + 4];
            const int sh = (kt & 3) * 8 + tig;

#pragma unroll
            for (int mt = 0; mt < 2; mt++) {
                unsigned t0 = mrow[2 * mt]     >> sh;
                unsigned t1 = mrow[2 * mt + 1] >> sh;

                float w00 = fmaxf(Ei[2 * mt]     * ef0.x, Fi[2 * mt]     * ef0.y);
                float w01 = fmaxf(Ei[2 * mt]     * ef1.x, Fi[2 * mt]     * ef1.y);
                float w10 = fmaxf(Ei[2 * mt + 1] * ef0.x, Fi[2 * mt + 1] * ef0.y);
                float w11 = fmaxf(Ei[2 * mt + 1] * ef1.x, Fi[2 * mt + 1] * ef1.y);

                unsigned a0 = (t0 & 1u)  ? (__float_as_uint(w00) & 0xFFFFE000u) : 0u;
                unsigned a2 = (t0 & 16u) ? (__float_as_uint(w01) & 0xFFFFE000u) : 0u;
                unsigned a1 = (t1 & 1u)  ? (__float_as_uint(w10) & 0xFFFFE000u) : 0u;
                unsigned a3 = (t1 & 16u) ? (__float_as_uint(w11) & 0xFFFFE000u) : 0u;

                rs[2 * mt]     += __uint_as_float(a0) + __uint_as_float(a2);
                rs[2 * mt + 1] += __uint_as_float(a1) + __uint_as_float(a3);

                mma_tf32(acc[mt][0], a0, a1, a2, a3, q0.x, q0.y);
                mma_tf32(acc[mt][1], a0, a1, a2, a3, q0.z, q0.w);
                mma_tf32(acc[mt][2], a0, a1, a2, a3, q1.x, q1.y);
                mma_tf32(acc[mt][3], a0, a1, a2, a3, q1.z, q1.w);
            }
        }
    }

#pragma unroll
    for (int m = 0; m < 4; m++) {
        rs[m] += __shfl_xor_sync(0xffffffffu, rs[m], 1);
        rs[m] += __shfl_xor_sync(0xffffffffu, rs[m], 2);
    }
    if (tig == 0) {
#pragma unroll
        for (int m = 0; m < 4; m++)
            d_rs[js][(size_t)(i0 + m * 8 + gid) * N_HEADS + h] = rs[m];
    }
#pragma unroll
    for (int mt = 0; mt < 2; mt++) {
        int r0 = i0 + mt * 16 + gid;
        int r1 = r0 + 8;
#pragma unroll
        for (int nt = 0; nt < 4; nt++) {
            int c = h * N_HIDDEN + nt * 8 + tig * 2;
            *(float2*)(&d_part[js][(size_t)r0 * OUT_FEAT + c]) =
                make_float2(acc[mt][nt][0], acc[mt][nt][1]);
            *(float2*)(&d_part[js][(size_t)r1 * OUT_FEAT + c]) =
                make_float2(acc[mt][nt][2], acc[mt][nt][3]);
        }
    }
}

// ---------------------------------------------------------------------------
// Kernel 3: reduce partials and normalize (unchanged).
// ---------------------------------------------------------------------------
__global__ __launch_bounds__(256) void reduce_kernel(float* __restrict__ out) {
    int t  = blockIdx.x * 256 + threadIdx.x;   // 0..262143
    int i  = t >> 6;
    int c4 = t & 63;
    int hh = c4 >> 3;

    float4 num = make_float4(0.f, 0.f, 0.f, 0.f);
    float den = 0.f;
#pragma unroll
    for (int s = 0; s < JSPLIT; s++) {
        float4 p = *(const float4*)(&d_part[s][(size_t)i * OUT_FEAT + c4 * 4]);
        num.x += p.x; num.y += p.y; num.z += p.z; num.w += p.w;
        den += d_rs[s][(size_t)i * N_HEADS + hh];
    }
    float inv = 1.0f / den;
    *(float4*)(out + (size_t)i * OUT_FEAT + c4 * 4) =
        make_float4(num.x * inv, num.y * inv, num.z * inv, num.w * inv);
}

// ---------------------------------------------------------------------------
// Launch
// ---------------------------------------------------------------------------
extern "C" void kernel_launch(void* const* d_in, const int* in_sizes, int n_in,
                              void* d_out, int out_size) {
    const float* h   = (const float*)d_in[0];   // [4096, 256]
    const float* W   = (const float*)d_in[1];   // [256, 256]
    const float* a   = (const float*)d_in[2];   // [64]
    const int*   adj = (const int*)d_in[3];     // [4096, 4096, 1]
    float* out = (float*)d_out;                 // [4096, 256]

    (void)in_sizes; (void)n_in; (void)out_size;

    dim3 g1(N_NODES / 64, N_HEADS / 2);
    gemm_fused_kernel<<<g1, 512>>>(h, W, a);

    attn_kernel<<<dim3(N_NODES / 32, JSPLIT), 256>>>(adj);

    reduce_kernel<<<(N_NODES * OUT_FEAT / 4) / 256, 256>>>(out);
}